// round 3
// baseline (speedup 1.0000x reference)
#include <cuda_runtime.h>
#include <cuda_bf16.h>

#define BB 4
#define CC 32
#define PP 65536
#define NW 16
#define NH 16
#define KK 256
#define PCH 1024                 // pixels per chunk
#define CTAS_PER_BATCH 32
#define CHUNKS_PER_CTA 2
#define THREADS 512
#define NWARPS 16
#define BINS_PER_WARP (KK / NWARPS)   // 16
#define FS 34                    // floats per pixel row (even for LDS.64, 34%32=2 keeps banks clean)

// smem: F_sh[PCH*FS] | A_sh[9*PCH] | plist[PCH] | cnt[KK] | offs[KK+1]
#define SMEM_FLOATS (PCH * FS + 9 * PCH + PCH + KK + KK + 1)
#define SMEM_BYTES (SMEM_FLOATS * 4)

// Accumulator scratch: [b][k][c<32]=fsum, [b][k][32]=wsum.
// Zero at module load; epilogue re-zeroes after reading -> replay-deterministic.
__device__ float g_fsum[BB * KK * (CC + 1)];

__global__ __launch_bounds__(THREADS, 1)
void spix_main(const float* __restrict__ feats,
               const float* __restrict__ assoc,
               const int*   __restrict__ idxmap) {
    extern __shared__ float sm[];
    float* F_sh  = sm;                         // [PCH][FS] pixel-major
    float* A_sh  = sm + PCH * FS;              // [9][PCH]
    int*   plist = (int*)(A_sh + 9 * PCH);     // [PCH] pixel ids sorted by base idx
    int*   cnt   = plist + PCH;                // [KK]
    int*   offs  = cnt + KK;                   // [KK+1]

    const int b    = blockIdx.x >> 5;
    const int s    = blockIdx.x & 31;
    const int tid  = threadIdx.x;
    const int wid  = tid >> 5;
    const int lane = tid & 31;
    const int grp  = lane >> 4;                // half-warp group: which of 2 entries
    const int cl   = lane & 15;                // channel pair index (channels 2cl, 2cl+1)

    if (tid < KK) cnt[tid] = 0;
    __syncthreads();

    for (int ch = 0; ch < CHUNKS_PER_CTA; ch++) {
        const int p0 = ((s << 1) + ch) << 10;

        // ---- stage F pixel-major: F_sh[pl*FS + c] = feats[b][c][p0+pl] ----
        // Thread: c = tid>>4, pixels pl = (tid&15) + 16*q. STS banks: (34*pl + c)&31
        // = (2*(tid&15) + c)&31 -> 32 distinct banks across the warp. Conflict-free.
        {
            const int c  = tid >> 4;
            const int l  = tid & 15;
            const float* src = feats + ((size_t)(b * CC + c)) * PP + p0 + l;
            float* dst = F_sh + (size_t)l * FS + c;
#pragma unroll
            for (int q = 0; q < 64; q++)
                dst[q * 16 * FS] = src[q * 16];
        }
        // ---- stage A: A_sh[j*PCH + pl] (coalesced float4) ----
        for (int t = tid; t < 9 * PCH / 4; t += THREADS) {
            const int j   = t >> 8;
            const int pl4 = (t & 255) << 2;
            float4 v = *(const float4*)(assoc + ((size_t)(b * 9 + j)) * PP + p0 + pl4);
            *(float4*)(A_sh + j * PCH + pl4) = v;
        }

        // ---- count pixels per base superpixel (2 px / thread) ----
        const int idxA = idxmap[(size_t)b * PP + p0 + tid];
        const int idxB = idxmap[(size_t)b * PP + p0 + 512 + tid];
        atomicAdd(&cnt[idxA], 1);
        atomicAdd(&cnt[idxB], 1);
        __syncthreads();

        // ---- exclusive scan (warp 0); writes offs + cursor copy into cnt ----
        if (wid == 0) {
            int running = 0;
            for (int g = 0; g < KK / 32; g++) {
                const int v = cnt[g * 32 + lane];
                int incl = v;
#pragma unroll
                for (int d = 1; d < 32; d <<= 1) {
                    int n = __shfl_up_sync(0xffffffffu, incl, d);
                    if (lane >= d) incl += n;
                }
                const int excl = running + incl - v;
                offs[g * 32 + lane] = excl;
                running += __shfl_sync(0xffffffffu, incl, 31);
            }
            if (lane == 0) offs[KK] = running;
        }
        __syncthreads();
        if (tid < KK) cnt[tid] = offs[tid];    // cursors
        __syncthreads();

        // ---- place pixel ids sorted by base idx ----
        plist[atomicAdd(&cnt[idxA], 1)] = tid;
        plist[atomicAdd(&cnt[idxB], 1)] = 512 + tid;
        __syncthreads();
        if (tid < KK) cnt[tid] = 0;            // re-zero for next chunk (gather doesn't read cnt)

        // ---- gather: warp owns 16 bins; 2 entries/iter (half-warp each) ----
        for (int sb = 0; sb < BINS_PER_WARP; sb++) {
            const int k  = wid * BINS_PER_WARP + sb;
            const int kx = k & 15, ky = k >> 4;
            float a0 = 0.f, a1 = 0.f, aw = 0.f;
#pragma unroll
            for (int j = 0; j < 9; j++) {
                const int sx = kx - (j % 3 - 1);
                const int sy = ky - (j / 3 - 1);
                if (sx < 0 || sx > 15 || sy < 0 || sy > 15) continue;
                const int src = sy * 16 + sx;
                const int beg = offs[src], end = offs[src + 1];
                const float* wb = A_sh + j * PCH;
                for (int e = beg; e < end; e += 2) {
                    const int  eg = e + grp;
                    const bool vv = eg < end;
                    const int  p  = plist[vv ? eg : e];
                    const float w = vv ? wb[p] : 0.f;
                    const float2 f = *(const float2*)(F_sh + (size_t)p * FS + 2 * cl);
                    a0 += w * f.x;
                    a1 += w * f.y;
                    aw += w;
                }
            }
            // merge the two half-warp groups, flush with fire-and-forget REDs
            a0 += __shfl_xor_sync(0xffffffffu, a0, 16);
            a1 += __shfl_xor_sync(0xffffffffu, a1, 16);
            aw += __shfl_xor_sync(0xffffffffu, aw, 16);
            float* gb = &g_fsum[(size_t)(b * KK + k) * (CC + 1)];
            if (lane < 16) {
                atomicAdd(gb + 2 * lane,     a0);
                atomicAdd(gb + 2 * lane + 1, a1);
            } else if (lane == 16) {
                atomicAdd(gb + CC, aw);
            }
        }
        __syncthreads();
    }
}

// One warp per (b,k): read 33 accumulators, write 32 outputs, reset to zero.
__global__ void epilogue(float* __restrict__ out) {
    const int gw   = (blockIdx.x * blockDim.x + threadIdx.x) >> 5;
    const int lane = threadIdx.x & 31;
    if (gw >= BB * KK) return;
    const int b = gw >> 8, k = gw & 255;
    float* base = &g_fsum[(size_t)gw * (CC + 1)];
    const float ws = base[CC];
    const float fs = base[lane];
    const float r  = (ws > 1e-16f) ? fs / ws : 0.f;
    out[((size_t)b * CC + lane) * KK + k] = r;
    __syncwarp();
    base[lane] = 0.f;
    if (lane == 0) base[CC] = 0.f;
}

extern "C" void kernel_launch(void* const* d_in, const int* in_sizes, int n_in,
                              void* d_out, int out_size) {
    const float* feats  = (const float*)d_in[0];
    const float* assoc  = (const float*)d_in[1];
    const int*   idxmap = (const int*)d_in[2];

    static int configured = 0;
    if (!configured) {
        cudaFuncSetAttribute(spix_main, cudaFuncAttributeMaxDynamicSharedMemorySize,
                             SMEM_BYTES);
        configured = 1;
    }

    spix_main<<<BB * CTAS_PER_BATCH, THREADS, SMEM_BYTES>>>(feats, assoc, idxmap);
    epilogue<<<(BB * KK * 32 + 255) / 256, 256>>>((float*)d_out);
}